// round 7
// baseline (speedup 1.0000x reference)
#include <cuda_runtime.h>
#include <math.h>

#define BATCH 512
#define LEN   256
#define DIM   64
#define HIDN  256
#define TOPK  128
#define NBINS 4096
#define CAND_CAP 2048

// ---------------- static scratch (no allocations allowed) ----------------
__device__ float g_M[DIM * DIM];
__device__ float g_u[DIM];
__device__ float g_v[DIM];
__device__ float g_cc;
__device__ float g_scores[(size_t)BATCH * LEN * LEN];      // 134 MB
__device__ float g_mm[BATCH * 2];
__device__ int   g_rows[BATCH * TOPK];
__device__ int   g_cols[BATCH * TOPK];
__device__ float g_wt[BATCH * TOPK];
__device__ float g_pooled[BATCH * HIDN];

// ---------------- kernel A: M = Wq Wk^T, u = Wq bk, v = Wk bq, cc = bq.bk ----
__global__ void kPrep(const float* __restrict__ Wq, const float* __restrict__ Wk,
                      const float* __restrict__ bq, const float* __restrict__ bk) {
    int tid = threadIdx.x;
    if (blockIdx.x < 16) {
        int idx = blockIdx.x * 256 + tid;
        int d  = idx >> 6;
        int dp = idx & 63;
        float acc = 0.f;
        #pragma unroll 8
        for (int h = 0; h < HIDN; h++) acc += Wq[d * HIDN + h] * Wk[dp * HIDN + h];
        g_M[idx] = acc;
    } else {
        if (tid < 64) {
            float a = 0.f;
            for (int h = 0; h < HIDN; h++) a += Wq[tid * HIDN + h] * bk[h];
            g_u[tid] = a;
        } else if (tid < 128) {
            int d = tid - 64;
            float a = 0.f;
            for (int h = 0; h < HIDN; h++) a += Wk[d * HIDN + h] * bq[h];
            g_v[d] = a;
        } else if (tid == 128) {
            float a = 0.f;
            for (int h = 0; h < HIDN; h++) a += bq[h] * bk[h];
            g_cc = a;
        }
    }
}

// ---------------- kernel C: scores[b] = scale*(x M x^T + A + C + cc), + min/max ----
// Fused: G = x@M computed in-smem (replaces the former kG kernel + g_Gt scratch).
#define SC_SMEM_FLOATS (64*260*2 + 64*65 + 256*2 + 512)
__global__ void kScores(const float* __restrict__ x) {
    extern __shared__ float sm[];
    float* sG   = sm;                 // [64 d'][260] : G^T
    float* sX   = sG + 64 * 260;      // [64 d][260]  : x^T
    float* sM   = sX + 64 * 260;      // [64 d][65 d']
    float* sA   = sM + 64 * 65;       // 256
    float* sC   = sA + 256;           // 256
    float* sred = sC + 256;           // 512

    int b = blockIdx.x, tid = threadIdx.x;
    const float* xb = x + (size_t)b * LEN * DIM;
    // load x^T: sX[d][m] = x[m][d]
    for (int t = tid; t < LEN * DIM; t += 256) {
        int m = t >> 6, d = t & 63;
        sX[d * 260 + m] = xb[m * DIM + d];
    }
    // load M with padded rows
    for (int t = tid; t < DIM * DIM; t += 256) {
        int d = t >> 6, dp = t & 63;
        sM[d * 65 + dp] = g_M[t];
    }
    __syncthreads();

    // compute G^T: sG[dp][l] = sum_d sM[d][dp] * sX[d][l]
    // thread t -> dp = t>>2, l-range = (t&3)*64 .. +63  (vectorized float4 over l)
    {
        int dp = tid >> 2;
        int lb = (tid & 3) * 64;
        float4 acc[16];
        #pragma unroll
        for (int v = 0; v < 16; v++) acc[v] = make_float4(0.f, 0.f, 0.f, 0.f);
        #pragma unroll 4
        for (int d = 0; d < DIM; d++) {
            float mval = sM[d * 65 + dp];
            const float4* xr = (const float4*)(sX + d * 260 + lb);
            #pragma unroll
            for (int v = 0; v < 16; v++) {
                float4 xv = xr[v];
                acc[v].x += mval * xv.x; acc[v].y += mval * xv.y;
                acc[v].z += mval * xv.z; acc[v].w += mval * xv.w;
            }
        }
        float4* gr = (float4*)(sG + dp * 260 + lb);
        #pragma unroll
        for (int v = 0; v < 16; v++) gr[v] = acc[v];
    }
    // A/C bias rows: sA[l] = x[l].u ; sC[l] = x[l].v  (one l per thread)
    {
        int l = tid;
        float a = 0.f, c = 0.f;
        #pragma unroll 8
        for (int d = 0; d < DIM; d++) {
            float xv = sX[d * 260 + l];
            a += xv * g_u[d];
            c += xv * g_v[d];
        }
        sA[l] = a; sC[l] = c;
    }
    float ccv = g_cc;
    __syncthreads();

    const float scale = 0.0625f;   // 256^-0.5
    float lmin = 3.4e38f, lmax = -3.4e38f;

    for (int iter = 0; iter < 16; iter++) {
        int T = iter * 256 + tid;
        int l0 = (T >> 6) * 4;
        int m0 = (T & 63) * 4;
        float a[4][4];
        #pragma unroll
        for (int r = 0; r < 4; r++)
            #pragma unroll
            for (int c = 0; c < 4; c++) a[r][c] = 0.f;

        #pragma unroll 8
        for (int d = 0; d < DIM; d++) {
            float4 gv = *(const float4*)(sG + d * 260 + l0);
            float4 xv = *(const float4*)(sX + d * 260 + m0);
            a[0][0] += gv.x * xv.x; a[0][1] += gv.x * xv.y; a[0][2] += gv.x * xv.z; a[0][3] += gv.x * xv.w;
            a[1][0] += gv.y * xv.x; a[1][1] += gv.y * xv.y; a[1][2] += gv.y * xv.z; a[1][3] += gv.y * xv.w;
            a[2][0] += gv.z * xv.x; a[2][1] += gv.z * xv.y; a[2][2] += gv.z * xv.z; a[2][3] += gv.z * xv.w;
            a[3][0] += gv.w * xv.x; a[3][1] += gv.w * xv.y; a[3][2] += gv.w * xv.z; a[3][3] += gv.w * xv.w;
        }
        #pragma unroll
        for (int r = 0; r < 4; r++) {
            float base = sA[l0 + r] + ccv;
            float4 o;
            o.x = scale * (a[r][0] + base + sC[m0 + 0]);
            o.y = scale * (a[r][1] + base + sC[m0 + 1]);
            o.z = scale * (a[r][2] + base + sC[m0 + 2]);
            o.w = scale * (a[r][3] + base + sC[m0 + 3]);
            lmin = fminf(lmin, fminf(fminf(o.x, o.y), fminf(o.z, o.w)));
            lmax = fmaxf(lmax, fmaxf(fmaxf(o.x, o.y), fmaxf(o.z, o.w)));
            *(float4*)(g_scores + ((size_t)b * LEN + l0 + r) * LEN + m0) = o;
        }
    }
    sred[tid] = lmin; sred[256 + tid] = lmax;
    __syncthreads();
    for (int s = 128; s > 0; s >>= 1) {
        if (tid < s) {
            sred[tid]       = fminf(sred[tid], sred[tid + s]);
            sred[256 + tid] = fmaxf(sred[256 + tid], sred[256 + tid + s]);
        }
        __syncthreads();
    }
    if (tid == 0) { g_mm[b * 2] = sred[0]; g_mm[b * 2 + 1] = sred[256]; }
}

// ---------------- kernel D: per-batch exact top-128 + softmax weights ----------------
__global__ void kTopK() {
    __shared__ unsigned int hist[NBINS];
    __shared__ float cvals[CAND_CAP];
    __shared__ int   cidx[CAND_CAP];
    __shared__ unsigned int cnt;
    __shared__ float s_thr;
    __shared__ float sred[256];

    int b = blockIdx.x, tid = threadIdx.x;
    const float* sc = g_scores + (size_t)b * LEN * LEN;
    float minv = g_mm[b * 2];
    float maxv = g_mm[b * 2 + 1];
    float range = fmaxf(maxv - minv, 1e-20f);
    float invw = (float)NBINS / range;
    float binw = range / (float)NBINS;

    for (int t = tid; t < NBINS; t += 256) hist[t] = 0u;
    if (tid == 0) cnt = 0u;
    __syncthreads();

    for (int t = tid; t < LEN * LEN; t += 256) {
        float v = sc[t];
        int bin = (int)((v - minv) * invw);
        bin = min(max(bin, 0), NBINS - 1);
        atomicAdd(&hist[bin], 1u);
    }
    __syncthreads();

    if (tid == 0) {
        unsigned int cum = 0;
        int t = NBINS - 1;
        for (; t > 0; t--) { cum += hist[t]; if (cum >= TOPK) break; }
        if (cum < TOPK) t = 0;
        int tc = max(t - 1, 0);          // one-bin safety margin
        s_thr = minv + (float)tc * binw;
    }
    __syncthreads();
    float thr = s_thr;

    for (int t = tid; t < LEN * LEN; t += 256) {
        float v = sc[t];
        if (v >= thr) {
            unsigned int p = atomicAdd(&cnt, 1u);
            if (p < CAND_CAP) { cvals[p] = v; cidx[p] = t; }
        }
    }
    __syncthreads();
    int C = (int)min(cnt, (unsigned int)CAND_CAP);
    for (int t = C + tid; t < CAND_CAP; t += 256) { cvals[t] = -3.4e38f; cidx[t] = 0; }
    __syncthreads();

    // bitonic sort (descending by value)
    for (int k = 2; k <= CAND_CAP; k <<= 1) {
        for (int j = k >> 1; j > 0; j >>= 1) {
            for (int i = tid; i < CAND_CAP; i += 256) {
                int ixj = i ^ j;
                if (ixj > i) {
                    float vi = cvals[i], vj = cvals[ixj];
                    bool descBlock = ((i & k) == 0);
                    if (descBlock ? (vi < vj) : (vi > vj)) {
                        cvals[i] = vj; cvals[ixj] = vi;
                        int t2 = cidx[i]; cidx[i] = cidx[ixj]; cidx[ixj] = t2;
                    }
                }
            }
            __syncthreads();
        }
    }

    float maxval = cvals[0];
    float e = 0.f;
    if (tid < TOPK) e = expf(cvals[tid] - maxval);
    sred[tid] = (tid < TOPK) ? e : 0.f;
    __syncthreads();
    for (int s = 128; s > 0; s >>= 1) {
        if (tid < s) sred[tid] += sred[tid + s];
        __syncthreads();
    }
    float denom = sred[0];
    if (tid < TOPK) {
        int idx = cidx[tid];
        g_rows[b * TOPK + tid] = idx >> 8;
        g_cols[b * TOPK + tid] = idx & 255;
        g_wt[b * TOPK + tid]   = e / denom;
    }
}

// ---------------- kernel E: pair features (layer1) + weighted pool + layer2 matvec ----
#define PR_SMEM_BYTES ((128*256 + 128*128 + 4*256 + 256 + 256 + 128 + 128) * 4 + 384 * 4)
__global__ void kPairs(const float* __restrict__ x,
                       const float* __restrict__ xi_w1, const float* __restrict__ xi_b1,
                       const float* __restrict__ xi_w2, const float* __restrict__ xi_b2,
                       const float* __restrict__ phi_w1, const float* __restrict__ phi_b1,
                       const float* __restrict__ phi_w2, const float* __restrict__ phi_b2) {
    extern __shared__ float sm[];
    float* sW1   = sm;                    // [128][256]
    float* sXpT  = sW1 + 128 * 256;       // [128 d][128 i]
    float* hpart = sXpT + 128 * 128;      // [4][256]
    float* hxs   = hpart + 4 * 256;       // 256
    float* hps   = hxs + 256;             // 256
    float* sw    = hps + 256;             // 128
    float* swxi  = sw + 128;              // 128
    int* srow  = (int*)(swxi + 128);      // 128
    int* scol  = srow + 128;              // 128
    int* dlist = scol + 128;              // 128
    __shared__ int   s_nd;
    __shared__ float s_swxi, s_swphi;

    int b = blockIdx.x, tid = threadIdx.x;

    for (int t = tid; t < 128 * HIDN; t += 256) sW1[t] = xi_w1[t];
    if (tid < TOPK) {
        srow[tid] = g_rows[b * TOPK + tid];
        scol[tid] = g_cols[b * TOPK + tid];
        sw[tid]   = g_wt[b * TOPK + tid];
    }
    __syncthreads();

    // build transposed pair matrix: rows 0..63 = x_row dims, 64..127 = x_col dims
    {
        int i = tid >> 1, half = tid & 1;
        int src = half ? scol[i] : srow[i];
        const float* xr = x + ((size_t)b * LEN + src) * DIM;
        #pragma unroll
        for (int dv = 0; dv < 16; dv++) {
            float4 v = *(const float4*)(xr + dv * 4);
            int d = half * 64 + dv * 4;
            sXpT[(d + 0) * 128 + i] = v.x;
            sXpT[(d + 1) * 128 + i] = v.y;
            sXpT[(d + 2) * 128 + i] = v.z;
            sXpT[(d + 3) * 128 + i] = v.w;
        }
    }
    if (tid == 0) {
        int nd = 0; float sphi = 0.f, sxi = 0.f;
        for (int i = 0; i < TOPK; i++) {
            if (srow[i] == scol[i]) { dlist[nd++] = i; sphi += sw[i]; }
            else sxi += sw[i];
        }
        s_nd = nd; s_swphi = sphi; s_swxi = sxi;
    }
    if (tid < TOPK) swxi[tid] = (srow[tid] == scol[tid]) ? 0.f : sw[tid];
    __syncthreads();

    // xi layer-1: h1[i][j], relu, weighted-accumulate into hbar_xi[j]
    int jt = tid & 63, ig = tid >> 6;
    int j0 = jt * 4;
    float4 b1v = *(const float4*)(xi_b1 + j0);
    float hb0 = 0.f, hb1 = 0.f, hb2 = 0.f, hb3 = 0.f;
    for (int it = ig * 8; it < ig * 8 + 8; it++) {
        int i0 = it * 4;
        float acc[4][4];
        #pragma unroll
        for (int r = 0; r < 4; r++) {
            acc[r][0] = b1v.x; acc[r][1] = b1v.y; acc[r][2] = b1v.z; acc[r][3] = b1v.w;
        }
        #pragma unroll 8
        for (int d = 0; d < 128; d++) {
            float4 xv = *(const float4*)(sXpT + d * 128 + i0);
            float4 wv = *(const float4*)(sW1 + d * 256 + j0);
            acc[0][0] += xv.x * wv.x; acc[0][1] += xv.x * wv.y; acc[0][2] += xv.x * wv.z; acc[0][3] += xv.x * wv.w;
            acc[1][0] += xv.y * wv.x; acc[1][1] += xv.y * wv.y; acc[1][2] += xv.y * wv.z; acc[1][3] += xv.y * wv.w;
            acc[2][0] += xv.z * wv.x; acc[2][1] += xv.z * wv.y; acc[2][2] += xv.z * wv.z; acc[2][3] += xv.z * wv.w;
            acc[3][0] += xv.w * wv.x; acc[3][1] += xv.w * wv.y; acc[3][2] += xv.w * wv.z; acc[3][3] += xv.w * wv.w;
        }
        #pragma unroll
        for (int r = 0; r < 4; r++) {
            float wi = swxi[i0 + r];
            hb0 += wi * fmaxf(acc[r][0], 0.f);
            hb1 += wi * fmaxf(acc[r][1], 0.f);
            hb2 += wi * fmaxf(acc[r][2], 0.f);
            hb3 += wi * fmaxf(acc[r][3], 0.f);
        }
    }
    hpart[ig * 256 + j0 + 0] = hb0;
    hpart[ig * 256 + j0 + 1] = hb1;
    hpart[ig * 256 + j0 + 2] = hb2;
    hpart[ig * 256 + j0 + 3] = hb3;
    __syncthreads();

    int j = tid;
    float hx = hpart[j] + hpart[256 + j] + hpart[512 + j] + hpart[768 + j];
    hxs[j] = hx;

    // phi path (diagonal pairs only — typically 0-2 per batch)
    float hp = 0.f;
    int nd = s_nd;
    for (int t = 0; t < nd; t++) {
        int i = dlist[t];
        float acc = phi_b1[j];
        #pragma unroll 8
        for (int d = 0; d < DIM; d++) acc += sXpT[d * 128 + i] * phi_w1[d * HIDN + j];
        hp += sw[i] * fmaxf(acc, 0.f);
    }
    hps[j] = hp;
    __syncthreads();

    // layer-2 folded into pooling: pooled = hbar_xi @ xi_w2 + swxi*xi_b2 (+ phi terms)
    float out = s_swxi * xi_b2[j];
    #pragma unroll 8
    for (int k = 0; k < HIDN; k++) out += hxs[k] * xi_w2[k * HIDN + j];
    if (nd > 0) {
        out += s_swphi * phi_b2[j];
        #pragma unroll 8
        for (int k = 0; k < HIDN; k++) out += hps[k] * phi_w2[k * HIDN + j];
    }
    g_pooled[b * HIDN + j] = out;
}

// ---------------- kernel F: rho MLP ----------------
__global__ void kRho(const float* __restrict__ w1, const float* __restrict__ b1,
                     const float* __restrict__ w2, const float* __restrict__ b2,
                     float* __restrict__ out) {
    __shared__ float p[HIDN];
    __shared__ float h[HIDN];
    int b = blockIdx.x, tid = threadIdx.x;
    p[tid] = g_pooled[b * HIDN + tid];
    __syncthreads();
    float acc = b1[tid];
    #pragma unroll 8
    for (int k = 0; k < HIDN; k++) acc += p[k] * w1[k * HIDN + tid];
    h[tid] = fmaxf(acc, 0.f);
    __syncthreads();
    if (tid < 128) {
        float o = b2[tid];
        #pragma unroll 8
        for (int k = 0; k < HIDN; k++) o += h[k] * w2[k * 128 + tid];
        out[b * 128 + tid] = o;
    }
}

// ---------------- launch ----------------
extern "C" void kernel_launch(void* const* d_in, const int* in_sizes, int n_in,
                              void* d_out, int out_size) {
    const float* x      = (const float*)d_in[0];
    const float* Wq     = (const float*)d_in[1];
    const float* bq     = (const float*)d_in[2];
    const float* Wk     = (const float*)d_in[3];
    const float* bk     = (const float*)d_in[4];
    const float* phi_w1 = (const float*)d_in[5];
    const float* phi_b1 = (const float*)d_in[6];
    const float* phi_w2 = (const float*)d_in[7];
    const float* phi_b2 = (const float*)d_in[8];
    const float* xi_w1  = (const float*)d_in[9];
    const float* xi_b1  = (const float*)d_in[10];
    const float* xi_w2  = (const float*)d_in[11];
    const float* xi_b2  = (const float*)d_in[12];
    const float* rho_w1 = (const float*)d_in[13];
    const float* rho_b1 = (const float*)d_in[14];
    const float* rho_w2 = (const float*)d_in[15];
    const float* rho_b2 = (const float*)d_in[16];
    float* out = (float*)d_out;

    int scSmem = SC_SMEM_FLOATS * sizeof(float);
    int prSmem = PR_SMEM_BYTES;
    cudaFuncSetAttribute(kScores, cudaFuncAttributeMaxDynamicSharedMemorySize, scSmem);
    cudaFuncSetAttribute(kPairs,  cudaFuncAttributeMaxDynamicSharedMemorySize, prSmem);

    kPrep<<<17, 256>>>(Wq, Wk, bq, bk);
    kScores<<<BATCH, 256, scSmem>>>(x);
    kTopK<<<BATCH, 256>>>();
    kPairs<<<BATCH, 256, prSmem>>>(x, xi_w1, xi_b1, xi_w2, xi_b2,
                                   phi_w1, phi_b1, phi_w2, phi_b2);
    kRho<<<BATCH, 256>>>(rho_w1, rho_b1, rho_w2, rho_b2, out);
}

// round 9
// speedup vs baseline: 1.2045x; 1.2045x over previous
#include <cuda_runtime.h>
#include <math.h>

#define BATCH 512
#define LEN   256
#define DIM   64
#define HIDN  256
#define TOPK  128
#define NBINS 4096
#define CAND  1024

// ---------------- static scratch ----------------
__device__ float g_M[DIM * DIM];
__device__ float g_u[DIM];
__device__ float g_v[DIM];
__device__ float g_cc;
__device__ int   g_rows[BATCH * TOPK];
__device__ int   g_cols[BATCH * TOPK];
__device__ float g_wt[BATCH * TOPK];
__device__ float g_pooled[BATCH * HIDN];

// ---------------- kernel A: M = Wq Wk^T, u = Wq bk, v = Wk bq, cc = bq.bk ----
__global__ void kPrep(const float* __restrict__ Wq, const float* __restrict__ Wk,
                      const float* __restrict__ bq, const float* __restrict__ bk) {
    int tid = threadIdx.x;
    if (blockIdx.x < 16) {
        int idx = blockIdx.x * 256 + tid;
        int d  = idx >> 6;
        int dp = idx & 63;
        float acc = 0.f;
        #pragma unroll 8
        for (int h = 0; h < HIDN; h++) acc += Wq[d * HIDN + h] * Wk[dp * HIDN + h];
        g_M[idx] = acc;
    } else {
        if (tid < 64) {
            float a = 0.f;
            for (int h = 0; h < HIDN; h++) a += Wq[tid * HIDN + h] * bk[h];
            g_u[tid] = a;
        } else if (tid < 128) {
            int d = tid - 64;
            float a = 0.f;
            for (int h = 0; h < HIDN; h++) a += Wk[d * HIDN + h] * bq[h];
            g_v[d] = a;
        } else if (tid == 128) {
            float a = 0.f;
            for (int h = 0; h < HIDN; h++) a += bq[h] * bk[h];
            g_cc = a;
        }
    }
}

// ---------------- fused kernel: scores (in registers) + exact top-128 + softmax ----
// smem floats: sG 16640 + sX 16640 + sM 4160 + sA 256 + sC 256 + hist 4096
//              + coarse 256 + cvals 1024 + cidx 1024 + wred 32
#define ST_SMEM_FLOATS (16640 + 16640 + 4160 + 256 + 256 + 4096 + 256 + 1024 + 1024 + 32)
__global__ void kScoresTopK(const float* __restrict__ x) {
    extern __shared__ float sm[];
    float* sG   = sm;                 // [64 d'][260] : G^T
    float* sX   = sG + 16640;         // [64 d][260]  : x^T
    float* sM   = sX + 16640;         // [64][65]
    float* sA   = sM + 4160;          // 256
    float* sC   = sA + 256;           // 256
    unsigned int* hist   = (unsigned int*)(sC + 256);    // 4096
    unsigned int* coarse = hist + NBINS;                  // 256
    float* cvals = (float*)(coarse + 256);                // 1024
    int*   cidx  = (int*)(cvals + CAND);                  // 1024
    float* wred  = (float*)(cidx + CAND);                 // 32
    __shared__ unsigned int s_cnt;
    __shared__ float s_thr, s_minv, s_binw;

    int b = blockIdx.x, tid = threadIdx.x;
    int lane = tid & 31, wid = tid >> 5;
    const float* xb = x + (size_t)b * LEN * DIM;

    // load x^T: sX[d][m] = x[m][d]
    for (int t = tid; t < LEN * DIM; t += 256) {
        int m = t >> 6, d = t & 63;
        sX[d * 260 + m] = xb[m * DIM + d];
    }
    for (int t = tid; t < DIM * DIM; t += 256) {
        int d = t >> 6, dp = t & 63;
        sM[d * 65 + dp] = g_M[t];
    }
    if (tid == 0) s_cnt = 0u;
    __syncthreads();

    // G^T: sG[dp][l] = sum_d sM[d][dp] * sX[d][l]
    {
        int dp = tid >> 2;
        int lb = (tid & 3) * 64;
        float4 acc[16];
        #pragma unroll
        for (int v = 0; v < 16; v++) acc[v] = make_float4(0.f, 0.f, 0.f, 0.f);
        #pragma unroll 4
        for (int d = 0; d < DIM; d++) {
            float mval = sM[d * 65 + dp];
            const float4* xr = (const float4*)(sX + d * 260 + lb);
            #pragma unroll
            for (int v = 0; v < 16; v++) {
                float4 xv = xr[v];
                acc[v].x += mval * xv.x; acc[v].y += mval * xv.y;
                acc[v].z += mval * xv.z; acc[v].w += mval * xv.w;
            }
        }
        float4* gr = (float4*)(sG + dp * 260 + lb);
        #pragma unroll
        for (int v = 0; v < 16; v++) gr[v] = acc[v];
    }
    // bias rows
    {
        int l = tid;
        float a = 0.f, c = 0.f;
        #pragma unroll 8
        for (int d = 0; d < DIM; d++) {
            float xv = sX[d * 260 + l];
            a += xv * g_u[d];
            c += xv * g_v[d];
        }
        sA[l] = a; sC[l] = c;
    }
    float ccv = g_cc;
    __syncthreads();

    const float scale = 0.0625f;   // 256^-0.5
    int lt = wid;                  // 0..7  (warp-uniform l tile)
    int mA = lane * 4;             // cols mA..mA+3 and mA+128..mA+131

    for (int chunk = 0; chunk < 4; chunk++) {
        int l0 = chunk * 64 + lt * 8;

        float acc[8][8];
        #pragma unroll
        for (int r = 0; r < 8; r++)
            #pragma unroll
            for (int c = 0; c < 8; c++) acc[r][c] = 0.f;

        #pragma unroll 4
        for (int d = 0; d < DIM; d++) {
            float4 g0 = *(const float4*)(sG + d * 260 + l0);
            float4 g1 = *(const float4*)(sG + d * 260 + l0 + 4);
            float4 xa = *(const float4*)(sX + d * 260 + mA);
            float4 xc = *(const float4*)(sX + d * 260 + mA + 128);
            float gv[8] = {g0.x, g0.y, g0.z, g0.w, g1.x, g1.y, g1.z, g1.w};
            float xv[8] = {xa.x, xa.y, xa.z, xa.w, xc.x, xc.y, xc.z, xc.w};
            #pragma unroll
            for (int r = 0; r < 8; r++)
                #pragma unroll
                for (int c = 0; c < 8; c++) acc[r][c] += gv[r] * xv[c];
        }
        // bias + scale, min/max
        float lmin = 3.4e38f, lmax = -3.4e38f;
        #pragma unroll
        for (int r = 0; r < 8; r++) {
            float base = sA[l0 + r] + ccv;
            #pragma unroll
            for (int c = 0; c < 8; c++) {
                int m = (c < 4) ? (mA + c) : (mA + 124 + c);
                float v = scale * (acc[r][c] + base + sC[m]);
                acc[r][c] = v;
                lmin = fminf(lmin, v);
                lmax = fmaxf(lmax, v);
            }
        }
        // block min/max reduce
        #pragma unroll
        for (int o = 16; o > 0; o >>= 1) {
            lmin = fminf(lmin, __shfl_xor_sync(0xffffffffu, lmin, o));
            lmax = fmaxf(lmax, __shfl_xor_sync(0xffffffffu, lmax, o));
        }
        if (lane == 0) { wred[wid] = lmin; wred[8 + wid] = lmax; }
        // clear hist while reduction lands
        for (int t = tid; t < NBINS; t += 256) hist[t] = 0u;
        __syncthreads();
        if (tid == 0) {
            float mn = wred[0], mx = wred[8];
            #pragma unroll
            for (int w = 1; w < 8; w++) {
                mn = fminf(mn, wred[w]);
                mx = fmaxf(mx, wred[8 + w]);
            }
            float range = fmaxf(mx - mn, 1e-20f);
            s_minv = mn;
            s_binw = range / (float)NBINS;
        }
        __syncthreads();
        float minv = s_minv;
        float invw = 1.0f / s_binw;

        // histogram from registers
        #pragma unroll
        for (int r = 0; r < 8; r++)
            #pragma unroll
            for (int c = 0; c < 8; c++) {
                int bin = (int)((acc[r][c] - minv) * invw);
                bin = min(max(bin, 0), NBINS - 1);
                atomicAdd(&hist[bin], 1u);
            }
        __syncthreads();
        // coarse sums (16 bins each)
        {
            unsigned int s = 0;
            #pragma unroll
            for (int k = 0; k < 16; k++) s += hist[tid * 16 + k];
            coarse[tid] = s;
        }
        __syncthreads();
        if (tid == 0) {
            unsigned int cum = 0;
            int cb = 0;
            for (int t = 255; t >= 0; t--) {
                if (cum + coarse[t] >= TOPK) { cb = t; break; }
                cum += coarse[t];
                if (t == 0) cb = 0;
            }
            int tbin = cb * 16;
            for (int f = cb * 16 + 15; f >= cb * 16; f--) {
                cum += hist[f];
                if (cum >= TOPK) { tbin = f; break; }
            }
            int tc = max(tbin - 1, 0);     // one-bin safety margin
            s_thr = minv + (float)tc * s_binw;
        }
        __syncthreads();
        float thr = s_thr;

        // collect candidates from registers
        #pragma unroll
        for (int r = 0; r < 8; r++)
            #pragma unroll
            for (int c = 0; c < 8; c++) {
                float v = acc[r][c];
                if (v >= thr) {
                    unsigned int p = atomicAdd(&s_cnt, 1u);
                    if (p < CAND) {
                        int m = (c < 4) ? (mA + c) : (mA + 124 + c);
                        cvals[p] = v;
                        cidx[p]  = (l0 + r) * LEN + m;
                    }
                }
            }
        __syncthreads();
    }

    // pad + bitonic sort (descending)
    int C = (int)min(s_cnt, (unsigned int)CAND);
    for (int t = C + tid; t < CAND; t += 256) { cvals[t] = -3.4e38f; cidx[t] = 0; }
    __syncthreads();
    for (int k = 2; k <= CAND; k <<= 1) {
        for (int j = k >> 1; j > 0; j >>= 1) {
            for (int i = tid; i < CAND; i += 256) {
                int ixj = i ^ j;
                if (ixj > i) {
                    float vi = cvals[i], vj = cvals[ixj];
                    bool descBlock = ((i & k) == 0);
                    if (descBlock ? (vi < vj) : (vi > vj)) {
                        cvals[i] = vj; cvals[ixj] = vi;
                        int t2 = cidx[i]; cidx[i] = cidx[ixj]; cidx[ixj] = t2;
                    }
                }
            }
            __syncthreads();
        }
    }

    // softmax over top-128
    __shared__ float sred[256];
    float maxval = cvals[0];
    float e = 0.f;
    if (tid < TOPK) e = expf(cvals[tid] - maxval);
    sred[tid] = (tid < TOPK) ? e : 0.f;
    __syncthreads();
    for (int s = 128; s > 0; s >>= 1) {
        if (tid < s) sred[tid] += sred[tid + s];
        __syncthreads();
    }
    float denom = sred[0];
    if (tid < TOPK) {
        int idx = cidx[tid];
        g_rows[b * TOPK + tid] = idx >> 8;
        g_cols[b * TOPK + tid] = idx & 255;
        g_wt[b * TOPK + tid]   = e / denom;
    }
}

// ---------------- kernel E: pair features (8x8 tiles) + weighted pool + layer2 ----
// smem floats: sW1 32768 + sXpT 16384 + hpart 2048 + hxs 256 + hps 256 + misc 640
#define PR_SMEM_FLOATS (32768 + 16384 + 2048 + 256 + 256 + 128 + 128 + 128 + 128 + 128)
__global__ void kPairs(const float* __restrict__ x,
                       const float* __restrict__ xi_w1, const float* __restrict__ xi_b1,
                       const float* __restrict__ xi_w2, const float* __restrict__ xi_b2,
                       const float* __restrict__ phi_w1, const float* __restrict__ phi_b1,
                       const float* __restrict__ phi_w2, const float* __restrict__ phi_b2) {
    extern __shared__ float sm[];
    float* sW1   = sm;                    // [128 d][256 j]
    float* sXpT  = sW1 + 32768;           // [128 d][128 i]
    float* hpart = sXpT + 16384;          // [8][256]
    float* hxs   = hpart + 2048;          // 256
    float* hps   = hxs + 256;             // 256
    float* sw    = hps + 256;             // 128
    float* swxi  = sw + 128;              // 128
    int* srow  = (int*)(swxi + 128);      // 128
    int* scol  = srow + 128;              // 128
    int* dlist = scol + 128;              // 128
    __shared__ int   s_nd;
    __shared__ float s_swxi, s_swphi;

    int b = blockIdx.x, tid = threadIdx.x;
    int lane = tid & 31, wid = tid >> 5;

    for (int t = tid; t < 128 * HIDN; t += 256) sW1[t] = xi_w1[t];
    if (tid < TOPK) {
        srow[tid] = g_rows[b * TOPK + tid];
        scol[tid] = g_cols[b * TOPK + tid];
        sw[tid]   = g_wt[b * TOPK + tid];
    }
    __syncthreads();

    // transposed pair matrix: rows 0..63 = x_row dims, 64..127 = x_col dims
    {
        int i = tid >> 1, half = tid & 1;
        int src = half ? scol[i] : srow[i];
        const float* xr = x + ((size_t)b * LEN + src) * DIM;
        #pragma unroll
        for (int dv = 0; dv < 16; dv++) {
            float4 v = *(const float4*)(xr + dv * 4);
            int d = half * 64 + dv * 4;
            sXpT[(d + 0) * 128 + i] = v.x;
            sXpT[(d + 1) * 128 + i] = v.y;
            sXpT[(d + 2) * 128 + i] = v.z;
            sXpT[(d + 3) * 128 + i] = v.w;
        }
    }
    if (tid == 0) {
        int nd = 0; float sphi = 0.f, sxi = 0.f;
        for (int i = 0; i < TOPK; i++) {
            if (srow[i] == scol[i]) { dlist[nd++] = i; sphi += sw[i]; }
            else sxi += sw[i];
        }
        s_nd = nd; s_swphi = sphi; s_swxi = sxi;
    }
    if (tid < TOPK) swxi[tid] = (srow[tid] == scol[tid]) ? 0.f : sw[tid];
    __syncthreads();

    // xi layer-1 with 8x8 register tiles; weighted relu accumulate into hbar[8]
    int jA = lane * 4;                 // j cols jA..+3 and jA+128..+131
    float4 b1a = *(const float4*)(xi_b1 + jA);
    float4 b1c = *(const float4*)(xi_b1 + jA + 128);
    float hbar[8] = {0.f, 0.f, 0.f, 0.f, 0.f, 0.f, 0.f, 0.f};

    #pragma unroll
    for (int iter = 0; iter < 2; iter++) {
        int i0 = wid * 8 + iter * 64;  // warp-uniform i tile
        float acc[8][8];
        #pragma unroll
        for (int r = 0; r < 8; r++) {
            acc[r][0] = b1a.x; acc[r][1] = b1a.y; acc[r][2] = b1a.z; acc[r][3] = b1a.w;
            acc[r][4] = b1c.x; acc[r][5] = b1c.y; acc[r][6] = b1c.z; acc[r][7] = b1c.w;
        }
        #pragma unroll 4
        for (int d = 0; d < 128; d++) {
            float4 x0 = *(const float4*)(sXpT + d * 128 + i0);
            float4 x1 = *(const float4*)(sXpT + d * 128 + i0 + 4);
            float4 wa = *(const float4*)(sW1 + d * 256 + jA);
            float4 wc = *(const float4*)(sW1 + d * 256 + jA + 128);
            float xv[8] = {x0.x, x0.y, x0.z, x0.w, x1.x, x1.y, x1.z, x1.w};
            float wv[8] = {wa.x, wa.y, wa.z, wa.w, wc.x, wc.y, wc.z, wc.w};
            #pragma unroll
            for (int r = 0; r < 8; r++)
                #pragma unroll
                for (int c = 0; c < 8; c++) acc[r][c] += xv[r] * wv[c];
        }
        #pragma unroll
        for (int r = 0; r < 8; r++) {
            float wi = swxi[i0 + r];
            #pragma unroll
            for (int c = 0; c < 8; c++) hbar[c] += wi * fmaxf(acc[r][c], 0.f);
        }
    }
    #pragma unroll
    for (int c = 0; c < 4; c++) {
        hpart[wid * 256 + jA + c]       = hbar[c];
        hpart[wid * 256 + jA + 128 + c] = hbar[4 + c];
    }
    __syncthreads();

    int j = tid;
    float hx = 0.f;
    #pragma unroll
    for (int g = 0; g < 8; g++) hx += hpart[g * 256 + j];
    hxs[j] = hx;

    // phi path (diagonal pairs only — typically 0-2 per batch)
    float hp = 0.f;
    int nd = s_nd;
    for (int t = 0; t < nd; t++) {
        int i = dlist[t];
        float acc = phi_b1[j];
        #pragma unroll 8
        for (int d = 0; d < DIM; d++) acc += sXpT[d * 128 + i] * phi_w1[d * HIDN + j];
        hp += sw[i] * fmaxf(acc, 0.f);
    }
    hps[j] = hp;
    __syncthreads();

    // layer-2 folded into pooling
    float out = s_swxi * xi_b2[j];
    #pragma unroll 8
    for (int k = 0; k < HIDN; k++) out += hxs[k] * xi_w2[k * HIDN + j];
    if (nd > 0) {
        out += s_swphi * phi_b2[j];
        #pragma unroll 8
        for (int k = 0; k < HIDN; k++) out += hps[k] * phi_w2[k * HIDN + j];
    }
    g_pooled[b * HIDN + j] = out;
}

// ---------------- kernel F: rho MLP ----------------
__global__ void kRho(const float* __restrict__ w1, const float* __restrict__ b1,
                     const float* __restrict__ w2, const float* __restrict__ b2,
                     float* __restrict__ out) {
    __shared__ float p[HIDN];
    __shared__ float h[HIDN];
    int b = blockIdx.x, tid = threadIdx.x;
    p[tid] = g_pooled[b * HIDN + tid];
    __syncthreads();
    float acc = b1[tid];
    #pragma unroll 8
    for (int k = 0; k < HIDN; k++) acc += p[k] * w1[k * HIDN + tid];
    h[tid] = fmaxf(acc, 0.f);
    __syncthreads();
    if (tid < 128) {
        float o = b2[tid];
        #pragma unroll 8
        for (int k = 0; k < HIDN; k++) o += h[k] * w2[k * 128 + tid];
        out[b * 128 + tid] = o;
    }
}

// ---------------- launch ----------------
extern "C" void kernel_launch(void* const* d_in, const int* in_sizes, int n_in,
                              void* d_out, int out_size) {
    const float* x      = (const float*)d_in[0];
    const float* Wq     = (const float*)d_in[1];
    const float* bq     = (const float*)d_in[2];
    const float* Wk     = (const float*)d_in[3];
    const float* bk     = (const float*)d_in[4];
    const float* phi_w1 = (const float*)d_in[5];
    const float* phi_b1 = (const float*)d_in[6];
    const float* phi_w2 = (const float*)d_in[7];
    const float* phi_b2 = (const float*)d_in[8];
    const float* xi_w1  = (const float*)d_in[9];
    const float* xi_b1  = (const float*)d_in[10];
    const float* xi_w2  = (const float*)d_in[11];
    const float* xi_b2  = (const float*)d_in[12];
    const float* rho_w1 = (const float*)d_in[13];
    const float* rho_b1 = (const float*)d_in[14];
    const float* rho_w2 = (const float*)d_in[15];
    const float* rho_b2 = (const float*)d_in[16];
    float* out = (float*)d_out;

    int stSmem = ST_SMEM_FLOATS * sizeof(float);
    int prSmem = PR_SMEM_FLOATS * sizeof(float);
    cudaFuncSetAttribute(kScoresTopK, cudaFuncAttributeMaxDynamicSharedMemorySize, stSmem);
    cudaFuncSetAttribute(kPairs,      cudaFuncAttributeMaxDynamicSharedMemorySize, prSmem);

    kPrep<<<17, 256>>>(Wq, Wk, bq, bk);
    kScoresTopK<<<BATCH, 256, stSmem>>>(x);
    kPairs<<<BATCH, 256, prSmem>>>(x, xi_w1, xi_b1, xi_w2, xi_b2,
                                   phi_w1, phi_b1, phi_w2, phi_b2);
    kRho<<<BATCH, 256>>>(rho_w1, rho_b1, rho_w2, rho_b2, out);
}